// round 11
// baseline (speedup 1.0000x reference)
#include <cuda_runtime.h>
#include <cuda_bf16.h>
#include <cuda_fp16.h>
#include <cstdint>

#define BATCH  4
#define CH     128
#define NTOK   4096
#define NGRP   8
#define CPG    16
#define LDB    136      // 16-bit smem leading dim; 17*16B -> ldmatrix conflict-free
#define LDF    133      // fp32 staging leading dim

// q scale: 128^-0.5 * log2(e)  (softmax uses raw ex2)
#define SCL_Q  (0.08838834764831845f * 1.4426950408889634f)
#define EXP_B  8.656170245333781f     // 6 * log2(e)

// ---------------- scratch ----------------------------------------------------
__device__ __nv_bfloat16 g_hb[(size_t)BATCH * NTOK * CH];    // gn out [n][c] bf16
__device__ __half        g_q [(size_t)BATCH * NTOK * CH];    // q [n][c] fp16 (scaled)
__device__ __half        g_k [(size_t)BATCH * NTOK * CH];    // k [m][c] fp16
__device__ __half        g_v [(size_t)BATCH * NTOK * CH];    // v [m][c] fp16
__device__ __nv_bfloat16 g_ht[(size_t)BATCH * NTOK * CH];    // attn out [n][c] bf16
__device__ float         g_part[256][2];                     // gn partial sums

// ---------------- PTX primitives ---------------------------------------------
__device__ __forceinline__ uint32_t sptr(const void* p) {
    return (uint32_t)__cvta_generic_to_shared(p);
}
__device__ __forceinline__ void ldsm_x4(uint32_t* r, uint32_t addr) {
    asm volatile("ldmatrix.sync.aligned.m8n8.x4.shared.b16 {%0,%1,%2,%3}, [%4];"
                 : "=r"(r[0]), "=r"(r[1]), "=r"(r[2]), "=r"(r[3]) : "r"(addr));
}
__device__ __forceinline__ void ldsm_x4_t(uint32_t* r, uint32_t addr) {
    asm volatile("ldmatrix.sync.aligned.m8n8.x4.trans.shared.b16 {%0,%1,%2,%3}, [%4];"
                 : "=r"(r[0]), "=r"(r[1]), "=r"(r[2]), "=r"(r[3]) : "r"(addr));
}
__device__ __forceinline__ void mma16816(float* d, const uint32_t* a,
                                         const uint32_t* b, const float* c) {
    asm volatile(
        "mma.sync.aligned.m16n8k16.row.col.f32.bf16.bf16.f32 "
        "{%0,%1,%2,%3}, {%4,%5,%6,%7}, {%8,%9}, {%10,%11,%12,%13};"
        : "=f"(d[0]), "=f"(d[1]), "=f"(d[2]), "=f"(d[3])
        : "r"(a[0]), "r"(a[1]), "r"(a[2]), "r"(a[3]),
          "r"(b[0]), "r"(b[1]),
          "f"(c[0]), "f"(c[1]), "f"(c[2]), "f"(c[3]));
}
__device__ __forceinline__ void mma16816h(float* d, const uint32_t* a,
                                          const uint32_t* b, const float* c) {
    asm volatile(
        "mma.sync.aligned.m16n8k16.row.col.f32.f16.f16.f32 "
        "{%0,%1,%2,%3}, {%4,%5,%6,%7}, {%8,%9}, {%10,%11,%12,%13};"
        : "=f"(d[0]), "=f"(d[1]), "=f"(d[2]), "=f"(d[3])
        : "r"(a[0]), "r"(a[1]), "r"(a[2]), "r"(a[3]),
          "r"(b[0]), "r"(b[1]),
          "f"(c[0]), "f"(c[1]), "f"(c[2]), "f"(c[3]));
}
__device__ __forceinline__ void cp_async16(uint32_t dst, const void* src) {
    asm volatile("cp.async.cg.shared.global [%0], [%1], 16;" :: "r"(dst), "l"(src));
}
#define CP_COMMIT()  asm volatile("cp.async.commit_group;")
#define CP_WAIT0()   asm volatile("cp.async.wait_group 0;")

__device__ __forceinline__ uint32_t packbf(float a, float b) {
    __nv_bfloat162 t = __floats2bfloat162_rn(a, b);
    return *reinterpret_cast<uint32_t*>(&t);
}
__device__ __forceinline__ uint32_t packhf(float a, float b) {
    __half2 t = __floats2half2_rn(a, b);
    return *reinterpret_cast<uint32_t*>(&t);
}
// P-fragment: {lo = 2^lo_in, hi = 2^hi_in} as f16x2
__device__ __forceinline__ uint32_t pack_ex2(float hi, float lo) {
    uint32_t t, d;
    asm("cvt.rn.f16x2.f32 %0, %1, %2;" : "=r"(t) : "f"(hi), "f"(lo));
    asm("ex2.approx.f16x2 %0, %1;" : "=r"(d) : "r"(t));
    return d;
}

// ---------------- GroupNorm phase 1: partial sums ----------------------------
__global__ void __launch_bounds__(256) gn_part(const float* __restrict__ x) {
    const int bg = blockIdx.x >> 3, slice = blockIdx.x & 7;
    const float* xp = x + (size_t)bg * CPG * NTOK + slice * 512;
    const int tid = threadIdx.x;

    float s = 0.f, ss = 0.f;
    for (int i = tid; i < CPG * 512; i += 256) {
        int c = i >> 9, t = i & 511;
        float v = xp[(size_t)c * NTOK + t];
        s += v; ss += v * v;
    }
    __shared__ float rs[256], rq[256];
    rs[tid] = s; rq[tid] = ss;
    __syncthreads();
    for (int o = 128; o > 0; o >>= 1) {
        if (tid < o) { rs[tid] += rs[tid + o]; rq[tid] += rq[tid + o]; }
        __syncthreads();
    }
    if (tid == 0) { g_part[blockIdx.x][0] = rs[0]; g_part[blockIdx.x][1] = rq[0]; }
}

// ---------------- GroupNorm phase 2 ------------------------------------------
__global__ void __launch_bounds__(256) gn_apply(const float* __restrict__ x,
                                                const float* __restrict__ scale,
                                                const float* __restrict__ bias) {
    const int bg = blockIdx.x >> 3, slice = blockIdx.x & 7;
    const int b = bg / NGRP, g = bg % NGRP;
    const float* xp = x + (size_t)bg * CPG * NTOK;
    const int tid = threadIdx.x;

    float s = 0.f, ss = 0.f;
    #pragma unroll
    for (int i = 0; i < 8; i++) {
        s  += g_part[bg * 8 + i][0];
        ss += g_part[bg * 8 + i][1];
    }
    const float mean = s / (float)(CPG * NTOK);
    const float var  = ss / (float)(CPG * NTOK) - mean * mean;
    const float inv  = rsqrtf(var + 1e-6f);

    float sc[CPG], bi[CPG];
    #pragma unroll
    for (int c = 0; c < CPG; c++) {
        sc[c] = scale[g * CPG + c] * inv;
        bi[c] = bias[g * CPG + c] - mean * sc[c];
    }
    #pragma unroll
    for (int t = 0; t < 2; t++) {
        const int n = slice * 512 + t * 256 + tid;
        union { __nv_bfloat16 h[16]; uint4 u[2]; } p;
        #pragma unroll
        for (int c = 0; c < CPG; c++)
            p.h[c] = __float2bfloat16(xp[(size_t)c * NTOK + n] * sc[c] + bi[c]);
        uint4* dst = reinterpret_cast<uint4*>(g_hb + ((size_t)b * NTOK + n) * CH + g * CPG);
        dst[0] = p.u[0]; dst[1] = p.u[1];
    }
}

// ---------------- fused QKV conv via mma (bf16 in, fp16 out) -----------------
#define CV_SMEM (4 * 34816)

__global__ void __launch_bounds__(256) conv_qkv(
        const float* __restrict__ Wq, const float* __restrict__ Bq,
        const float* __restrict__ Wk, const float* __restrict__ Bk,
        const float* __restrict__ Wv, const float* __restrict__ Bv) {
    extern __shared__ char smem[];
    __nv_bfloat16* Hs = reinterpret_cast<__nv_bfloat16*>(smem);
    __nv_bfloat16* Wsm[3] = {
        reinterpret_cast<__nv_bfloat16*>(smem + 34816),
        reinterpret_cast<__nv_bfloat16*>(smem + 2 * 34816),
        reinterpret_cast<__nv_bfloat16*>(smem + 3 * 34816) };
    const float* Wg[3] = { Wq, Wk, Wv };
    const float* Bg[3] = { Bq, Bk, Bv };

    const int b = blockIdx.y, n0 = blockIdx.x * 128;
    const int tid = threadIdx.x, lane = tid & 31, wid = tid >> 5;

    for (int i = tid; i < 128 * 16; i += 256) {
        int r = i >> 4, ch = i & 15;
        *reinterpret_cast<uint4*>(Hs + r * LDB + ch * 8) =
            *reinterpret_cast<const uint4*>(g_hb + ((size_t)b * NTOK + n0 + r) * CH + ch * 8);
    }
    for (int t = 0; t < 3; t++)
        for (int i = tid; i < 128 * 32; i += 256) {
            int o = i >> 5, c4 = i & 31;
            float4 f = *reinterpret_cast<const float4*>(Wg[t] + (size_t)o * CH + c4 * 4);
            union { __nv_bfloat16 h[4]; uint2 u; } p;
            p.h[0] = __float2bfloat16(f.x); p.h[1] = __float2bfloat16(f.y);
            p.h[2] = __float2bfloat16(f.z); p.h[3] = __float2bfloat16(f.w);
            *reinterpret_cast<uint2*>(Wsm[t] + o * LDB + c4 * 4) = p.u;
        }
    __syncthreads();

    uint32_t qa[8][4];
    {
        uint32_t mi = lane >> 3;
        uint32_t arow = wid * 16 + (mi & 1) * 8 + (lane & 7);
        uint32_t acol = (mi >> 1) * 8;
        uint32_t aaddr = sptr(Hs) + (arow * LDB + acol) * 2;
        #pragma unroll
        for (int kc = 0; kc < 8; kc++) ldsm_x4(qa[kc], aaddr + kc * 32);
    }
    const uint32_t boff = (((lane >> 4) * 8 + (lane & 7)) * LDB + ((lane >> 3) & 1) * 8) * 2;
    const int g = lane >> 2, tq = lane & 3;
    const size_t row_lo = (size_t)b * NTOK + n0 + wid * 16 + g;

    uint16_t* Og[3] = { reinterpret_cast<uint16_t*>(g_q),
                        reinterpret_cast<uint16_t*>(g_k),
                        reinterpret_cast<uint16_t*>(g_v) };
    #pragma unroll
    for (int t = 0; t < 3; t++) {
        float S[16][4];
        #pragma unroll
        for (int j = 0; j < 16; j++)
            #pragma unroll
            for (int e = 0; e < 4; e++) S[j][e] = 0.f;
        const uint32_t wbase = sptr(Wsm[t]) + boff;
        #pragma unroll
        for (int kc = 0; kc < 8; kc++) {
            uint32_t wb[8][4];
            #pragma unroll
            for (int p = 0; p < 8; p++)
                ldsm_x4(wb[p], wbase + (p * 16 * LDB + kc * 16) * 2);
            #pragma unroll
            for (int p = 0; p < 8; p++) {
                mma16816(S[2 * p],     qa[kc], &wb[p][0], S[2 * p]);
                mma16816(S[2 * p + 1], qa[kc], &wb[p][2], S[2 * p + 1]);
            }
        }
        const float scl = (t == 0) ? SCL_Q : 1.0f;
        uint16_t* out = Og[t];
        #pragma unroll
        for (int p = 0; p < 8; p++) {
            #pragma unroll
            for (int half = 0; half < 2; half++) {
                const int col = p * 16 + half * 8 + tq * 2;
                const float b0 = __ldg(Bg[t] + col), b1 = __ldg(Bg[t] + col + 1);
                const float* Sj = S[2 * p + half];
                *reinterpret_cast<uint32_t*>(&out[row_lo * CH + col]) =
                    packhf((Sj[0] + b0) * scl, (Sj[1] + b1) * scl);
                *reinterpret_cast<uint32_t*>(&out[(row_lo + 8) * CH + col]) =
                    packhf((Sj[2] + b0) * scl, (Sj[3] + b1) * scl);
            }
        }
    }
}

// ---------------- flash attention: PV pipelined one iter behind QK -----------
// 64 q-rows, 4 warps, 2 blocks/SM. K double-buffered, V triple-buffered.
// Q staged through Vb[2] (first overwritten at iter 1, after barriers).
#define FTILE   17408                 // [64][136] 16-bit
#define FL_SMEM (5 * FTILE)           // K0 K1 V0 V1 V2 = 87040

__global__ void __launch_bounds__(128, 2) flash_attn() {
    extern __shared__ char smem[];
    char* Kb[2] = { smem,             smem + FTILE };
    char* Vb[3] = { smem + 2 * FTILE, smem + 3 * FTILE, smem + 4 * FTILE };

    const int b   = blockIdx.y;
    const int n0  = blockIdx.x * 64;
    const int tid = threadIdx.x;
    const int lane = tid & 31, wid = tid >> 5;   // 4 warps x 16 rows

    // prefetch kv-tile 0; stage Q into Vb[2]
    {
        uint32_t kd = sptr(Kb[0]), vd = sptr(Vb[0]);
        const __half* ks = g_k + (size_t)b * NTOK * CH;
        const __half* vs = g_v + (size_t)b * NTOK * CH;
        for (int i = tid; i < 1024; i += 128) {
            int r = i >> 4, ch = i & 15;
            cp_async16(kd + (r * LDB + ch * 8) * 2, ks + (size_t)r * CH + ch * 8);
            cp_async16(vd + (r * LDB + ch * 8) * 2, vs + (size_t)r * CH + ch * 8);
        }
        CP_COMMIT();
    }
    {
        __half* Qs = reinterpret_cast<__half*>(Vb[2]);
        for (int i = tid; i < 64 * 16; i += 128) {
            int r = i >> 4, ch = i & 15;
            *reinterpret_cast<uint4*>(Qs + r * LDB + ch * 8) =
                *reinterpret_cast<const uint4*>(g_q + ((size_t)b * NTOK + n0 + r) * CH + ch * 8);
        }
    }
    __syncthreads();

    uint32_t qa[8][4];
    {
        uint32_t mi = lane >> 3;
        uint32_t qrow = wid * 16 + (mi & 1) * 8 + (lane & 7);
        uint32_t qcol = (mi >> 1) * 8;
        uint32_t qaddr = sptr(Vb[2]) + (qrow * LDB + qcol) * 2;
        #pragma unroll
        for (int kc = 0; kc < 8; kc++) ldsm_x4(qa[kc], qaddr + kc * 32);
    }

    const uint32_t boffk = (((lane >> 4) * 8 + (lane & 7)) * LDB + ((lane >> 3) & 1) * 8) * 2;
    const uint32_t boffv = ((((lane >> 3) & 1) * 8 + (lane & 7)) * LDB + (lane >> 4) * 8) * 2;
    const uint32_t ones[2] = { 0x3C003C00u, 0x3C003C00u };   // fp16 {1,1}

    float O[16][4];
    #pragma unroll
    for (int j = 0; j < 16; j++)
        #pragma unroll
        for (int e = 0; e < 4; e++) O[j][e] = 0.f;
    float Lacc[4] = { 0.f, 0.f, 0.f, 0.f };
    uint32_t pf[4][4];    // P fragments of PREVIOUS iter

    for (int mc = 0; mc < 64; mc++) {
        CP_WAIT0();
        __syncthreads();
        const int kcur = mc & 1;
        if (mc + 1 < 64) {
            const int m1 = (mc + 1) * 64;
            uint32_t kd = sptr(Kb[kcur ^ 1]), vd = sptr(Vb[(mc + 1) % 3]);
            const __half* ks = g_k + ((size_t)b * NTOK + m1) * CH;
            const __half* vs = g_v + ((size_t)b * NTOK + m1) * CH;
            for (int i = tid; i < 1024; i += 128) {
                int r = i >> 4, ch = i & 15;
                cp_async16(kd + (r * LDB + ch * 8) * 2, ks + (size_t)r * CH + ch * 8);
                cp_async16(vd + (r * LDB + ch * 8) * 2, vs + (size_t)r * CH + ch * 8);
            }
            CP_COMMIT();
        }

        // QK(mc) interleaved with PV(mc-1); both pure tensor work
        float S[8][4];
        #pragma unroll
        for (int j = 0; j < 8; j++)
            #pragma unroll
            for (int e = 0; e < 4; e++) S[j][e] = -EXP_B;
        const uint32_t kbase = sptr(Kb[kcur]) + boffk;
        const uint32_t vbase = sptr(Vb[(mc + 2) % 3]) + boffv;   // (mc-1) mod 3
        #pragma unroll
        for (int kc = 0; kc < 8; kc++) {
            uint32_t kb[4][4];
            #pragma unroll
            for (int p = 0; p < 4; p++)
                ldsm_x4(kb[p], kbase + (p * 16 * LDB + kc * 16) * 2);
            #pragma unroll
            for (int p = 0; p < 4; p++) {
                mma16816h(S[2 * p],     qa[kc], &kb[p][0], S[2 * p]);
                mma16816h(S[2 * p + 1], qa[kc], &kb[p][2], S[2 * p + 1]);
            }
            if (mc > 0 && (kc & 1)) {
                const int k2 = kc >> 1;
                uint32_t vb[8][4];
                #pragma unroll
                for (int p = 0; p < 8; p++)
                    ldsm_x4_t(vb[p], vbase + (k2 * 16 * LDB + p * 16) * 2);
                #pragma unroll
                for (int p = 0; p < 8; p++) {
                    mma16816h(O[2 * p],     pf[k2], &vb[p][0], O[2 * p]);
                    mma16816h(O[2 * p + 1], pf[k2], &vb[p][2], O[2 * p + 1]);
                }
            }
        }

        // exp -> new P fragments (consumed next iter); row sums via ones-mma
        #pragma unroll
        for (int k2 = 0; k2 < 4; k2++) {
            pf[k2][0] = pack_ex2(S[2 * k2][1],     S[2 * k2][0]);
            pf[k2][1] = pack_ex2(S[2 * k2][3],     S[2 * k2][2]);
            pf[k2][2] = pack_ex2(S[2 * k2 + 1][1], S[2 * k2 + 1][0]);
            pf[k2][3] = pack_ex2(S[2 * k2 + 1][3], S[2 * k2 + 1][2]);
        }
        #pragma unroll
        for (int k2 = 0; k2 < 4; k2++)
            mma16816h(Lacc, pf[k2], ones, Lacc);
    }

    // drain: PV(63) — tile 63 lives in Vb[63 % 3 = 0]
    {
        const uint32_t vbase = sptr(Vb[0]) + boffv;
        #pragma unroll
        for (int k2 = 0; k2 < 4; k2++) {
            uint32_t vb[8][4];
            #pragma unroll
            for (int p = 0; p < 8; p++)
                ldsm_x4_t(vb[p], vbase + (k2 * 16 * LDB + p * 16) * 2);
            #pragma unroll
            for (int p = 0; p < 8; p++) {
                mma16816h(O[2 * p],     pf[k2], &vb[p][0], O[2 * p]);
                mma16816h(O[2 * p + 1], pf[k2], &vb[p][2], O[2 * p + 1]);
            }
        }
    }

    const float ilo = 1.f / Lacc[0];
    const float ihi = 1.f / Lacc[2];
    const int grp = lane >> 2, tq = lane & 3;
    const size_t row_lo = (size_t)b * NTOK + n0 + wid * 16 + grp;
    const size_t row_hi = row_lo + 8;
    #pragma unroll
    for (int j = 0; j < 16; j++) {
        int col = j * 8 + tq * 2;
        *reinterpret_cast<uint32_t*>(&g_ht[row_lo * CH + col]) =
            packbf(O[j][0] * ilo, O[j][1] * ilo);
        *reinterpret_cast<uint32_t*>(&g_ht[row_hi * CH + col]) =
            packbf(O[j][2] * ihi, O[j][3] * ihi);
    }
}

// ---------------- proj conv via mma + residual (64-token tiles) --------------
#define PJ_SMEM (17408 + 34816 + 64 * LDF * 4)

__global__ void __launch_bounds__(256) conv_proj(
        const float* __restrict__ W, const float* __restrict__ bias,
        const float* __restrict__ X, float* __restrict__ Out) {
    extern __shared__ char smem[];
    __nv_bfloat16* Hs  = reinterpret_cast<__nv_bfloat16*>(smem);
    __nv_bfloat16* Wsm = reinterpret_cast<__nv_bfloat16*>(smem + 17408);
    float* Os = reinterpret_cast<float*>(smem + 17408 + 34816);

    const int b = blockIdx.y, n0 = blockIdx.x * 64;
    const int tid = threadIdx.x, lane = tid & 31, wid = tid >> 5;
    const int wr = wid & 3, wc = wid >> 2;

    for (int i = tid; i < 64 * 16; i += 256) {
        int r = i >> 4, ch = i & 15;
        *reinterpret_cast<uint4*>(Hs + r * LDB + ch * 8) =
            *reinterpret_cast<const uint4*>(g_ht + ((size_t)b * NTOK + n0 + r) * CH + ch * 8);
    }
    for (int i = tid; i < 128 * 32; i += 256) {
        int o = i >> 5, c4 = i & 31;
        float4 f = *reinterpret_cast<const float4*>(W + (size_t)o * CH + c4 * 4);
        union { __nv_bfloat16 h[4]; uint2 u; } p;
        p.h[0] = __float2bfloat16(f.x); p.h[1] = __float2bfloat16(f.y);
        p.h[2] = __float2bfloat16(f.z); p.h[3] = __float2bfloat16(f.w);
        *reinterpret_cast<uint2*>(Wsm + o * LDB + c4 * 4) = p.u;
    }
    __syncthreads();

    uint32_t qa[8][4];
    {
        uint32_t mi = lane >> 3;
        uint32_t arow = wr * 16 + (mi & 1) * 8 + (lane & 7);
        uint32_t acol = (mi >> 1) * 8;
        uint32_t aaddr = sptr(Hs) + (arow * LDB + acol) * 2;
        #pragma unroll
        for (int kc = 0; kc < 8; kc++) ldsm_x4(qa[kc], aaddr + kc * 32);
    }
    const uint32_t boff = (((lane >> 4) * 8 + (lane & 7)) * LDB + ((lane >> 3) & 1) * 8) * 2;

    float S[8][4];
    #pragma unroll
    for (int j = 0; j < 8; j++)
        #pragma unroll
        for (int e = 0; e < 4; e++) S[j][e] = 0.f;
    const uint32_t wbase = sptr(Wsm) + boff + (wc * 64) * LDB * 2;
    #pragma unroll
    for (int kc = 0; kc < 8; kc++) {
        uint32_t wb[4][4];
        #pragma unroll
        for (int p = 0; p < 4; p++)
            ldsm_x4(wb[p], wbase + (p * 16 * LDB + kc * 16) * 2);
        #pragma unroll
        for (int p = 0; p < 4; p++) {
            mma16816(S[2 * p],     qa[kc], &wb[p][0], S[2 * p]);
            mma16816(S[2 * p + 1], qa[kc], &wb[p][2], S[2 * p + 1]);
        }
    }
    const int g = lane >> 2, tq = lane & 3;
    #pragma unroll
    for (int p = 0; p < 4; p++)
        #pragma unroll
        for (int half = 0; half < 2; half++) {
            const int col = wc * 64 + p * 16 + half * 8 + tq * 2;
            const float* Sj = S[2 * p + half];
            float* r0 = Os + (wr * 16 + g) * LDF + col;
            float* r1 = Os + (wr * 16 + g + 8) * LDF + col;
            r0[0] = Sj[0]; r0[1] = Sj[1];
            r1[0] = Sj[2]; r1[1] = Sj[3];
        }
    __syncthreads();

    for (int i = tid; i < 128 * 64; i += 256) {
        const int o = i >> 6, n = i & 63;
        const size_t idx = ((size_t)b * CH + o) * NTOK + n0 + n;
        Out[idx] = Os[n * LDF + o] + __ldg(bias + o) + X[idx];
    }
}

// ---------------- launch -----------------------------------------------------
extern "C" void kernel_launch(void* const* d_in, const int* in_sizes, int n_in,
                              void* d_out, int out_size) {
    const float* x        = (const float*)d_in[0];
    const float* gn_scale = (const float*)d_in[1];
    const float* gn_bias  = (const float*)d_in[2];
    const float* wq = (const float*)d_in[3];
    const float* bq = (const float*)d_in[4];
    const float* wk = (const float*)d_in[5];
    const float* bk = (const float*)d_in[6];
    const float* wv = (const float*)d_in[7];
    const float* bv = (const float*)d_in[8];
    const float* wp = (const float*)d_in[9];
    const float* bp = (const float*)d_in[10];
    float* out = (float*)d_out;

    cudaFuncSetAttribute(conv_qkv,   cudaFuncAttributeMaxDynamicSharedMemorySize, CV_SMEM);
    cudaFuncSetAttribute(flash_attn, cudaFuncAttributeMaxDynamicSharedMemorySize, FL_SMEM);
    cudaFuncSetAttribute(conv_proj,  cudaFuncAttributeMaxDynamicSharedMemorySize, PJ_SMEM);

    gn_part <<<256, 256>>>(x);
    gn_apply<<<256, 256>>>(x, gn_scale, gn_bias);
    conv_qkv<<<dim3(32, BATCH), 256, CV_SMEM>>>(wq, bq, wk, bk, wv, bv);
    flash_attn<<<dim3(64, BATCH), 128, FL_SMEM>>>();
    conv_proj<<<dim3(64, BATCH), 256, PJ_SMEM>>>(wp, bp, x, out);
}

// round 12
// speedup vs baseline: 1.2554x; 1.2554x over previous
#include <cuda_runtime.h>
#include <cuda_bf16.h>
#include <cuda_fp16.h>
#include <cstdint>

#define BATCH  4
#define CH     128
#define NTOK   4096
#define NGRP   8
#define CPG    16
#define LDB    136      // 16-bit smem leading dim; 17*16B -> ldmatrix conflict-free
#define LDF    133      // fp32 staging leading dim

// q scale: 128^-0.5 * log2(e)  (softmax uses raw ex2)
#define SCL_Q  (0.08838834764831845f * 1.4426950408889634f)
#define EXP_B  8.656170245333781f     // 6 * log2(e)

// ---------------- scratch ----------------------------------------------------
__device__ __half g_q [(size_t)BATCH * NTOK * CH];    // q [n][c] fp16 (scaled)
__device__ __half g_k [(size_t)BATCH * NTOK * CH];    // k [m][c] fp16
__device__ __half g_v [(size_t)BATCH * NTOK * CH];    // v [m][c] fp16
__device__ __half g_ht[(size_t)BATCH * NTOK * CH];    // attn out [n][c] fp16
__device__ float  g_part[256][2];                     // gn partial sums

// ---------------- PTX primitives ---------------------------------------------
__device__ __forceinline__ uint32_t sptr(const void* p) {
    return (uint32_t)__cvta_generic_to_shared(p);
}
__device__ __forceinline__ void ldsm_x4(uint32_t* r, uint32_t addr) {
    asm volatile("ldmatrix.sync.aligned.m8n8.x4.shared.b16 {%0,%1,%2,%3}, [%4];"
                 : "=r"(r[0]), "=r"(r[1]), "=r"(r[2]), "=r"(r[3]) : "r"(addr));
}
__device__ __forceinline__ void ldsm_x4_t(uint32_t* r, uint32_t addr) {
    asm volatile("ldmatrix.sync.aligned.m8n8.x4.trans.shared.b16 {%0,%1,%2,%3}, [%4];"
                 : "=r"(r[0]), "=r"(r[1]), "=r"(r[2]), "=r"(r[3]) : "r"(addr));
}
__device__ __forceinline__ void mma16816h(float* d, const uint32_t* a,
                                          const uint32_t* b, const float* c) {
    asm volatile(
        "mma.sync.aligned.m16n8k16.row.col.f32.f16.f16.f32 "
        "{%0,%1,%2,%3}, {%4,%5,%6,%7}, {%8,%9}, {%10,%11,%12,%13};"
        : "=f"(d[0]), "=f"(d[1]), "=f"(d[2]), "=f"(d[3])
        : "r"(a[0]), "r"(a[1]), "r"(a[2]), "r"(a[3]),
          "r"(b[0]), "r"(b[1]),
          "f"(c[0]), "f"(c[1]), "f"(c[2]), "f"(c[3]));
}
__device__ __forceinline__ void cp_async16(uint32_t dst, const void* src) {
    asm volatile("cp.async.cg.shared.global [%0], [%1], 16;" :: "r"(dst), "l"(src));
}
#define CP_COMMIT()  asm volatile("cp.async.commit_group;")
#define CP_WAIT0()   asm volatile("cp.async.wait_group 0;")

__device__ __forceinline__ uint32_t packhf(float a, float b) {
    __half2 t = __floats2half2_rn(a, b);
    return *reinterpret_cast<uint32_t*>(&t);
}
// P-fragment: {lo = 2^lo_in, hi = 2^hi_in} as f16x2
__device__ __forceinline__ uint32_t pack_ex2(float hi, float lo) {
    uint32_t t, d;
    asm("cvt.rn.f16x2.f32 %0, %1, %2;" : "=r"(t) : "f"(hi), "f"(lo));
    asm("ex2.approx.f16x2 %0, %1;" : "=r"(d) : "r"(t));
    return d;
}

// ---------------- GroupNorm phase 1: partial sums ----------------------------
__global__ void __launch_bounds__(256) gn_part(const float* __restrict__ x) {
    const int bg = blockIdx.x >> 3, slice = blockIdx.x & 7;
    const float* xp = x + (size_t)bg * CPG * NTOK + slice * 512;
    const int tid = threadIdx.x;

    float s = 0.f, ss = 0.f;
    for (int i = tid; i < CPG * 512; i += 256) {
        int c = i >> 9, t = i & 511;
        float v = xp[(size_t)c * NTOK + t];
        s += v; ss += v * v;
    }
    __shared__ float rs[256], rq[256];
    rs[tid] = s; rq[tid] = ss;
    __syncthreads();
    for (int o = 128; o > 0; o >>= 1) {
        if (tid < o) { rs[tid] += rs[tid + o]; rq[tid] += rq[tid + o]; }
        __syncthreads();
    }
    if (tid == 0) { g_part[blockIdx.x][0] = rs[0]; g_part[blockIdx.x][1] = rq[0]; }
}

// ---------------- fused GN-apply + QKV conv via mma --------------------------
// Normalizes x on the fly while staging the H tile (transposed to [n][c] fp16).
#define CV_SMEM (4 * 34816)

__global__ void __launch_bounds__(256) conv_qkv(
        const float* __restrict__ x,
        const float* __restrict__ gsc, const float* __restrict__ gbi,
        const float* __restrict__ Wq, const float* __restrict__ Bq,
        const float* __restrict__ Wk, const float* __restrict__ Bk,
        const float* __restrict__ Wv, const float* __restrict__ Bv) {
    extern __shared__ char smem[];
    __half* Hs = reinterpret_cast<__half*>(smem);
    __half* Wsm[3] = {
        reinterpret_cast<__half*>(smem + 34816),
        reinterpret_cast<__half*>(smem + 2 * 34816),
        reinterpret_cast<__half*>(smem + 3 * 34816) };
    __shared__ float sc_s[128], bi_s[128];
    const float* Wg[3] = { Wq, Wk, Wv };
    const float* Bg[3] = { Bq, Bk, Bv };

    const int b = blockIdx.y, n0 = blockIdx.x * 128;
    const int tid = threadIdx.x, lane = tid & 31, wid = tid >> 5;

    // per-channel norm params from g_part
    if (tid < 128) {
        const int grp = tid >> 4;
        const int bg = b * NGRP + grp;
        float s = 0.f, ss = 0.f;
        #pragma unroll
        for (int i = 0; i < 8; i++) {
            s += g_part[bg * 8 + i][0]; ss += g_part[bg * 8 + i][1];
        }
        const float mean = s * (1.f / 65536.f);
        const float var  = ss * (1.f / 65536.f) - mean * mean;
        const float inv  = rsqrtf(var + 1e-6f);
        const float scv  = gsc[tid] * inv;
        sc_s[tid] = scv;
        bi_s[tid] = gbi[tid] - mean * scv;
    }
    __syncthreads();

    // stage H tile: read x [c][n] coalesced, write Hs [n][c] fp16
    {
        const int nl = tid & 127, chalf = (tid >> 7) * 64;
        const float* xb = x + (size_t)b * CH * NTOK + n0 + nl;
        #pragma unroll 4
        for (int c2 = 0; c2 < 32; c2++) {
            const int c = chalf + c2 * 2;
            float v0 = xb[(size_t)c * NTOK]       * sc_s[c]     + bi_s[c];
            float v1 = xb[(size_t)(c + 1) * NTOK] * sc_s[c + 1] + bi_s[c + 1];
            *reinterpret_cast<uint32_t*>(&Hs[nl * LDB + c]) = packhf(v0, v1);
        }
    }
    // stage weights fp32 -> fp16
    for (int t = 0; t < 3; t++)
        for (int i = tid; i < 128 * 32; i += 256) {
            int o = i >> 5, c4 = i & 31;
            float4 f = *reinterpret_cast<const float4*>(Wg[t] + (size_t)o * CH + c4 * 4);
            uint2 u;
            u.x = packhf(f.x, f.y); u.y = packhf(f.z, f.w);
            *reinterpret_cast<uint2*>(Wsm[t] + o * LDB + c4 * 4) = u;
        }
    __syncthreads();

    uint32_t qa[8][4];
    {
        uint32_t mi = lane >> 3;
        uint32_t arow = wid * 16 + (mi & 1) * 8 + (lane & 7);
        uint32_t acol = (mi >> 1) * 8;
        uint32_t aaddr = sptr(Hs) + (arow * LDB + acol) * 2;
        #pragma unroll
        for (int kc = 0; kc < 8; kc++) ldsm_x4(qa[kc], aaddr + kc * 32);
    }
    const uint32_t boff = (((lane >> 4) * 8 + (lane & 7)) * LDB + ((lane >> 3) & 1) * 8) * 2;
    const int g = lane >> 2, tq = lane & 3;
    const size_t row_lo = (size_t)b * NTOK + n0 + wid * 16 + g;

    uint16_t* Og[3] = { reinterpret_cast<uint16_t*>(g_q),
                        reinterpret_cast<uint16_t*>(g_k),
                        reinterpret_cast<uint16_t*>(g_v) };
    #pragma unroll
    for (int t = 0; t < 3; t++) {
        float S[16][4];
        #pragma unroll
        for (int j = 0; j < 16; j++)
            #pragma unroll
            for (int e = 0; e < 4; e++) S[j][e] = 0.f;
        const uint32_t wbase = sptr(Wsm[t]) + boff;
        #pragma unroll
        for (int kc = 0; kc < 8; kc++) {
            uint32_t wb[8][4];
            #pragma unroll
            for (int p = 0; p < 8; p++)
                ldsm_x4(wb[p], wbase + (p * 16 * LDB + kc * 16) * 2);
            #pragma unroll
            for (int p = 0; p < 8; p++) {
                mma16816h(S[2 * p],     qa[kc], &wb[p][0], S[2 * p]);
                mma16816h(S[2 * p + 1], qa[kc], &wb[p][2], S[2 * p + 1]);
            }
        }
        const float scl = (t == 0) ? SCL_Q : 1.0f;
        uint16_t* out = Og[t];
        #pragma unroll
        for (int p = 0; p < 8; p++) {
            #pragma unroll
            for (int half = 0; half < 2; half++) {
                const int col = p * 16 + half * 8 + tq * 2;
                const float b0 = __ldg(Bg[t] + col), b1 = __ldg(Bg[t] + col + 1);
                const float* Sj = S[2 * p + half];
                *reinterpret_cast<uint32_t*>(&out[row_lo * CH + col]) =
                    packhf((Sj[0] + b0) * scl, (Sj[1] + b1) * scl);
                *reinterpret_cast<uint32_t*>(&out[(row_lo + 8) * CH + col]) =
                    packhf((Sj[2] + b0) * scl, (Sj[3] + b1) * scl);
            }
        }
    }
}

// ---------------- flash attention (R10-validated structure, fp16) ------------
// 64 q-rows, 4 warps, 2 blocks/SM. m-tiles of 64, K/V double-buffered.
#define FTILE   17408                 // [64][136] 16-bit
#define FL_SMEM (5 * FTILE)           // K0 K1 V0 V1 Q = 87040

__global__ void __launch_bounds__(128, 2) flash_attn() {
    extern __shared__ char smem[];
    char* Kb[2] = { smem,             smem + FTILE };
    char* Vb[2] = { smem + 2 * FTILE, smem + 3 * FTILE };
    __half* Qs = reinterpret_cast<__half*>(smem + 4 * FTILE);

    const int b   = blockIdx.y;
    const int n0  = blockIdx.x * 64;
    const int tid = threadIdx.x;
    const int lane = tid & 31, wid = tid >> 5;   // 4 warps x 16 rows

    for (int i = tid; i < 64 * 16; i += 128) {
        int r = i >> 4, ch = i & 15;
        *reinterpret_cast<uint4*>(Qs + r * LDB + ch * 8) =
            *reinterpret_cast<const uint4*>(g_q + ((size_t)b * NTOK + n0 + r) * CH + ch * 8);
    }
    {
        uint32_t kd = sptr(Kb[0]), vd = sptr(Vb[0]);
        const __half* ks = g_k + (size_t)b * NTOK * CH;
        const __half* vs = g_v + (size_t)b * NTOK * CH;
        for (int i = tid; i < 1024; i += 128) {
            int r = i >> 4, ch = i & 15;
            cp_async16(kd + (r * LDB + ch * 8) * 2, ks + (size_t)r * CH + ch * 8);
            cp_async16(vd + (r * LDB + ch * 8) * 2, vs + (size_t)r * CH + ch * 8);
        }
        CP_COMMIT();
    }
    __syncthreads();

    uint32_t qa[8][4];
    {
        uint32_t mi = lane >> 3;
        uint32_t qrow = wid * 16 + (mi & 1) * 8 + (lane & 7);
        uint32_t qcol = (mi >> 1) * 8;
        uint32_t qaddr = sptr(Qs) + (qrow * LDB + qcol) * 2;
        #pragma unroll
        for (int kc = 0; kc < 8; kc++) ldsm_x4(qa[kc], qaddr + kc * 32);
    }

    const uint32_t boffk = (((lane >> 4) * 8 + (lane & 7)) * LDB + ((lane >> 3) & 1) * 8) * 2;
    const uint32_t boffv = ((((lane >> 3) & 1) * 8 + (lane & 7)) * LDB + (lane >> 4) * 8) * 2;
    const uint32_t ones[2] = { 0x3C003C00u, 0x3C003C00u };   // fp16 {1,1}

    float O[16][4];
    #pragma unroll
    for (int j = 0; j < 16; j++)
        #pragma unroll
        for (int e = 0; e < 4; e++) O[j][e] = 0.f;
    float Lacc[4] = { 0.f, 0.f, 0.f, 0.f };

    for (int mc = 0; mc < 64; mc++) {
        CP_WAIT0();
        __syncthreads();
        const int cur = mc & 1;
        if (mc + 1 < 64) {
            const int m1 = (mc + 1) * 64;
            uint32_t kd = sptr(Kb[cur ^ 1]), vd = sptr(Vb[cur ^ 1]);
            const __half* ks = g_k + ((size_t)b * NTOK + m1) * CH;
            const __half* vs = g_v + ((size_t)b * NTOK + m1) * CH;
            for (int i = tid; i < 1024; i += 128) {
                int r = i >> 4, ch = i & 15;
                cp_async16(kd + (r * LDB + ch * 8) * 2, ks + (size_t)r * CH + ch * 8);
                cp_async16(vd + (r * LDB + ch * 8) * 2, vs + (size_t)r * CH + ch * 8);
            }
            CP_COMMIT();
        }

        float S[8][4];
        #pragma unroll
        for (int j = 0; j < 8; j++)
            #pragma unroll
            for (int e = 0; e < 4; e++) S[j][e] = -EXP_B;
        const uint32_t kbase = sptr(Kb[cur]) + boffk;
        #pragma unroll
        for (int kc = 0; kc < 8; kc++) {
            uint32_t kb[4][4];
            #pragma unroll
            for (int p = 0; p < 4; p++)
                ldsm_x4(kb[p], kbase + (p * 16 * LDB + kc * 16) * 2);
            #pragma unroll
            for (int p = 0; p < 4; p++) {
                mma16816h(S[2 * p],     qa[kc], &kb[p][0], S[2 * p]);
                mma16816h(S[2 * p + 1], qa[kc], &kb[p][2], S[2 * p + 1]);
            }
        }

        uint32_t pf[4][4];
        #pragma unroll
        for (int k2 = 0; k2 < 4; k2++) {
            pf[k2][0] = pack_ex2(S[2 * k2][1],     S[2 * k2][0]);
            pf[k2][1] = pack_ex2(S[2 * k2][3],     S[2 * k2][2]);
            pf[k2][2] = pack_ex2(S[2 * k2 + 1][1], S[2 * k2 + 1][0]);
            pf[k2][3] = pack_ex2(S[2 * k2 + 1][3], S[2 * k2 + 1][2]);
        }
        #pragma unroll
        for (int k2 = 0; k2 < 4; k2++)
            mma16816h(Lacc, pf[k2], ones, Lacc);

        const uint32_t vbase = sptr(Vb[cur]) + boffv;
        #pragma unroll
        for (int k2 = 0; k2 < 4; k2++) {
            uint32_t vb[8][4];
            #pragma unroll
            for (int p = 0; p < 8; p++)
                ldsm_x4_t(vb[p], vbase + (k2 * 16 * LDB + p * 16) * 2);
            #pragma unroll
            for (int p = 0; p < 8; p++) {
                mma16816h(O[2 * p],     pf[k2], &vb[p][0], O[2 * p]);
                mma16816h(O[2 * p + 1], pf[k2], &vb[p][2], O[2 * p + 1]);
            }
        }
    }

    const float ilo = 1.f / Lacc[0];
    const float ihi = 1.f / Lacc[2];
    const int grp = lane >> 2, tq = lane & 3;
    const size_t row_lo = (size_t)b * NTOK + n0 + wid * 16 + grp;
    const size_t row_hi = row_lo + 8;
    #pragma unroll
    for (int j = 0; j < 16; j++) {
        int col = j * 8 + tq * 2;
        *reinterpret_cast<uint32_t*>(&g_ht[row_lo * CH + col]) =
            packhf(O[j][0] * ilo, O[j][1] * ilo);
        *reinterpret_cast<uint32_t*>(&g_ht[row_hi * CH + col]) =
            packhf(O[j][2] * ihi, O[j][3] * ihi);
    }
}

// ---------------- proj conv via mma + residual (64-token tiles) --------------
#define PJ_SMEM (17408 + 34816 + 64 * LDF * 4)

__global__ void __launch_bounds__(256) conv_proj(
        const float* __restrict__ W, const float* __restrict__ bias,
        const float* __restrict__ X, float* __restrict__ Out) {
    extern __shared__ char smem[];
    __half* Hs  = reinterpret_cast<__half*>(smem);
    __half* Wsm = reinterpret_cast<__half*>(smem + 17408);
    float* Os = reinterpret_cast<float*>(smem + 17408 + 34816);

    const int b = blockIdx.y, n0 = blockIdx.x * 64;
    const int tid = threadIdx.x, lane = tid & 31, wid = tid >> 5;
    const int wr = wid & 3, wc = wid >> 2;

    for (int i = tid; i < 64 * 16; i += 256) {
        int r = i >> 4, ch = i & 15;
        *reinterpret_cast<uint4*>(Hs + r * LDB + ch * 8) =
            *reinterpret_cast<const uint4*>(g_ht + ((size_t)b * NTOK + n0 + r) * CH + ch * 8);
    }
    for (int i = tid; i < 128 * 32; i += 256) {
        int o = i >> 5, c4 = i & 31;
        float4 f = *reinterpret_cast<const float4*>(W + (size_t)o * CH + c4 * 4);
        uint2 u;
        u.x = packhf(f.x, f.y); u.y = packhf(f.z, f.w);
        *reinterpret_cast<uint2*>(Wsm + o * LDB + c4 * 4) = u;
    }
    __syncthreads();

    uint32_t qa[8][4];
    {
        uint32_t mi = lane >> 3;
        uint32_t arow = wr * 16 + (mi & 1) * 8 + (lane & 7);
        uint32_t acol = (mi >> 1) * 8;
        uint32_t aaddr = sptr(Hs) + (arow * LDB + acol) * 2;
        #pragma unroll
        for (int kc = 0; kc < 8; kc++) ldsm_x4(qa[kc], aaddr + kc * 32);
    }
    const uint32_t boff = (((lane >> 4) * 8 + (lane & 7)) * LDB + ((lane >> 3) & 1) * 8) * 2;

    float S[8][4];
    #pragma unroll
    for (int j = 0; j < 8; j++)
        #pragma unroll
        for (int e = 0; e < 4; e++) S[j][e] = 0.f;
    const uint32_t wbase = sptr(Wsm) + boff + (wc * 64) * LDB * 2;
    #pragma unroll
    for (int kc = 0; kc < 8; kc++) {
        uint32_t wb[4][4];
        #pragma unroll
        for (int p = 0; p < 4; p++)
            ldsm_x4(wb[p], wbase + (p * 16 * LDB + kc * 16) * 2);
        #pragma unroll
        for (int p = 0; p < 4; p++) {
            mma16816h(S[2 * p],     qa[kc], &wb[p][0], S[2 * p]);
            mma16816h(S[2 * p + 1], qa[kc], &wb[p][2], S[2 * p + 1]);
        }
    }
    const int g = lane >> 2, tq = lane & 3;
    #pragma unroll
    for (int p = 0; p < 4; p++)
        #pragma unroll
        for (int half = 0; half < 2; half++) {
            const int col = wc * 64 + p * 16 + half * 8 + tq * 2;
            const float* Sj = S[2 * p + half];
            float* r0 = Os + (wr * 16 + g) * LDF + col;
            float* r1 = Os + (wr * 16 + g + 8) * LDF + col;
            r0[0] = Sj[0]; r0[1] = Sj[1];
            r1[0] = Sj[2]; r1[1] = Sj[3];
        }
    __syncthreads();

    for (int i = tid; i < 128 * 64; i += 256) {
        const int o = i >> 6, n = i & 63;
        const size_t idx = ((size_t)b * CH + o) * NTOK + n0 + n;
        Out[idx] = Os[n * LDF + o] + __ldg(bias + o) + X[idx];
    }
}

// ---------------- launch -----------------------------------------------------
extern "C" void kernel_launch(void* const* d_in, const int* in_sizes, int n_in,
                              void* d_out, int out_size) {
    const float* x        = (const float*)d_in[0];
    const float* gn_scale = (const float*)d_in[1];
    const float* gn_bias  = (const float*)d_in[2];
    const float* wq = (const float*)d_in[3];
    const float* bq = (const float*)d_in[4];
    const float* wk = (const float*)d_in[5];
    const float* bk = (const float*)d_in[6];
    const float* wv = (const float*)d_in[7];
    const float* bv = (const float*)d_in[8];
    const float* wp = (const float*)d_in[9];
    const float* bp = (const float*)d_in[10];
    float* out = (float*)d_out;

    cudaFuncSetAttribute(conv_qkv,   cudaFuncAttributeMaxDynamicSharedMemorySize, CV_SMEM);
    cudaFuncSetAttribute(flash_attn, cudaFuncAttributeMaxDynamicSharedMemorySize, FL_SMEM);
    cudaFuncSetAttribute(conv_proj,  cudaFuncAttributeMaxDynamicSharedMemorySize, PJ_SMEM);

    gn_part <<<256, 256>>>(x);
    conv_qkv<<<dim3(32, BATCH), 256, CV_SMEM>>>(x, gn_scale, gn_bias,
                                                wq, bq, wk, bk, wv, bv);
    flash_attn<<<dim3(64, BATCH), 128, FL_SMEM>>>();
    conv_proj<<<dim3(64, BATCH), 256, PJ_SMEM>>>(wp, bp, x, out);
}